// round 3
// baseline (speedup 1.0000x reference)
#include <cuda_runtime.h>
#include <math.h>

#define Nn 50000
#define Ee 640000
#define Dd 128
#define FFd 256
#define CC 5
#define LL 6
#define BN_EPS 1e-5f

// ---------------- static scratch (no allocations allowed) ----------------
__device__ float g_X[(size_t)Nn * Dd];
__device__ float g_Q[(size_t)Nn * Dd];
__device__ float g_K[(size_t)Nn * Dd];
__device__ float g_V[(size_t)Nn * Dd];
__device__ float g_ATT[(size_t)Nn * Dd];
__device__ float g_A[(size_t)Nn * Dd];
__device__ float g_Hbuf[(size_t)Nn * FFd];
__device__ float g_T[(size_t)Nn * Dd];

__device__ int g_cnt[Nn];
__device__ int g_fill[Nn];
__device__ int g_rowptr[Nn + 1];
__device__ int g_esrc[Ee];
__device__ int g_blocksum[64];

__device__ float g_sum[Dd];
__device__ float g_sumsq[Dd];
__device__ float g_scale[Dd];
__device__ float g_shift[Dd];

// ---------------- small utility kernels ----------------
__global__ void copy_in_kernel(const float* __restrict__ src, float* __restrict__ dst, int n) {
    int i = blockIdx.x * blockDim.x + threadIdx.x;
    int stride = gridDim.x * blockDim.x;
    for (; i < n; i += stride) dst[i] = src[i];
}

__global__ void zero_csr_kernel() {
    int i = blockIdx.x * blockDim.x + threadIdx.x;
    int stride = gridDim.x * blockDim.x;
    for (; i < Nn; i += stride) { g_cnt[i] = 0; g_fill[i] = 0; }
}

__global__ void count_kernel(const int* __restrict__ dst) {
    int e = blockIdx.x * blockDim.x + threadIdx.x;
    if (e < Ee) atomicAdd(&g_cnt[dst[e]], 1);
}

// inclusive scan per 1024-chunk -> g_rowptr[i+1], chunk totals -> g_blocksum
__global__ void scan_chunk_kernel() {
    __shared__ int s[1024];
    int tid = threadIdx.x;
    int i = blockIdx.x * 1024 + tid;
    int v = (i < Nn) ? g_cnt[i] : 0;
    s[tid] = v;
    __syncthreads();
    for (int off = 1; off < 1024; off <<= 1) {
        int t = 0;
        if (tid >= off) t = s[tid - off];
        __syncthreads();
        s[tid] += t;
        __syncthreads();
    }
    if (i < Nn) g_rowptr[i + 1] = s[tid];
    if (tid == 1023) g_blocksum[blockIdx.x] = s[1023];
    if (blockIdx.x == 0 && tid == 0) g_rowptr[0] = 0;
}

__global__ void scan_blocks_kernel(int numChunks) {
    if (threadIdx.x == 0 && blockIdx.x == 0) {
        int run = 0;
        for (int c = 0; c < numChunks; c++) {
            int t = g_blocksum[c];
            g_blocksum[c] = run;
            run += t;
        }
    }
}

__global__ void scan_add_kernel() {
    int i = blockIdx.x * blockDim.x + threadIdx.x;
    if (i < Nn) g_rowptr[i + 1] += g_blocksum[i >> 10];
}

__global__ void fill_kernel(const int* __restrict__ src, const int* __restrict__ dst) {
    int e = blockIdx.x * blockDim.x + threadIdx.x;
    if (e < Ee) {
        int d = dst[e];
        int pos = atomicAdd(&g_fill[d], 1);
        g_esrc[g_rowptr[d] + pos] = src[e];
    }
}

// ---------------- GEMM: C[M,Nc] = A[M,K] @ B[K,Nc] (+bias)(+relu) ----------------
// BM=BN=128, BK=8, 256 threads, 8x8 per thread, fp32
// NOTE: no minBlocksPerMultiprocessor clause -> no 128-reg cap -> no acc spill.
__global__ __launch_bounds__(256) void gemm_kernel(
    const float* __restrict__ A, const float* __restrict__ B,
    const float* __restrict__ bias, float* __restrict__ C,
    int M, int K, int Nc, int fuseRelu)
{
    __shared__ float As[8][128];
    __shared__ float Bs[8][128];
    int tid = threadIdx.x;
    int bm = blockIdx.x * 128;
    int bn = blockIdx.y * 128;
    int tx = tid & 15;        // 0..15 -> cols
    int ty = tid >> 4;        // 0..15 -> rows
    float acc[8][8];
#pragma unroll
    for (int i = 0; i < 8; i++)
#pragma unroll
        for (int j = 0; j < 8; j++) acc[i][j] = 0.f;

    int arow = tid >> 1;            // 0..127
    int acol = (tid & 1) * 4;       // 0 or 4
    int brow = tid >> 5;            // 0..7
    int bcol = (tid & 31) * 4;      // 0..124
    int garow = bm + arow;
    const float* Aptr = A + (size_t)garow * K + acol;
    const float* Bptr = B + (size_t)brow * Nc + bn + bcol;

    for (int k0 = 0; k0 < K; k0 += 8) {
        float4 av = make_float4(0.f, 0.f, 0.f, 0.f);
        if (garow < M) av = *(const float4*)(Aptr + k0);
        As[acol + 0][arow] = av.x;
        As[acol + 1][arow] = av.y;
        As[acol + 2][arow] = av.z;
        As[acol + 3][arow] = av.w;
        float4 bv = *(const float4*)(Bptr + (size_t)k0 * Nc);
        *(float4*)&Bs[brow][bcol] = bv;
        __syncthreads();
#pragma unroll
        for (int k = 0; k < 8; k++) {
            float ar[8], br[8];
            *(float4*)&ar[0] = *(const float4*)&As[k][ty * 8];
            *(float4*)&ar[4] = *(const float4*)&As[k][ty * 8 + 4];
            *(float4*)&br[0] = *(const float4*)&Bs[k][tx * 8];
            *(float4*)&br[4] = *(const float4*)&Bs[k][tx * 8 + 4];
#pragma unroll
            for (int i = 0; i < 8; i++)
#pragma unroll
                for (int j = 0; j < 8; j++) acc[i][j] += ar[i] * br[j];
        }
        __syncthreads();
    }

    float bvals[8];
#pragma unroll
    for (int j = 0; j < 8; j++) bvals[j] = bias ? bias[bn + tx * 8 + j] : 0.f;

#pragma unroll
    for (int i = 0; i < 8; i++) {
        int row = bm + ty * 8 + i;
        if (row < M) {
            float o[8];
#pragma unroll
            for (int j = 0; j < 8; j++) {
                float v = acc[i][j] + bvals[j];
                if (fuseRelu) v = fmaxf(v, 0.f);
                o[j] = v;
            }
            float* cp = C + (size_t)row * Nc + bn + tx * 8;
            *(float4*)cp = *(float4*)&o[0];
            *(float4*)(cp + 4) = *(float4*)&o[4];
        }
    }
}

// ---------------- edge-restricted MHA: one warp per dst node, online softmax ----------------
__global__ __launch_bounds__(256) void attn_kernel(
    const float* __restrict__ q, const float* __restrict__ k,
    const float* __restrict__ v, float* __restrict__ out)
{
    int gwarp = (blockIdx.x * blockDim.x + threadIdx.x) >> 5;
    if (gwarp >= Nn) return;
    int lane = threadIdx.x & 31;

    float4 qv = *(const float4*)(q + (size_t)gwarp * Dd + lane * 4);
    float m = -INFINITY;
    float l = 0.f;
    float4 acc = make_float4(0.f, 0.f, 0.f, 0.f);

    int beg = g_rowptr[gwarp];
    int end = g_rowptr[gwarp + 1];
    for (int it = beg; it < end; it++) {
        int sn = g_esrc[it];
        const float4 kv = *(const float4*)(k + (size_t)sn * Dd + lane * 4);
        float partial = qv.x * kv.x + qv.y * kv.y + qv.z * kv.z + qv.w * kv.w;
        // reduce over the 4 lanes covering one head (DH=16 = 4 lanes x 4 floats)
        partial += __shfl_xor_sync(0xffffffffu, partial, 1);
        partial += __shfl_xor_sync(0xffffffffu, partial, 2);
        float s = partial * 0.25f;   // 1/sqrt(16)
        float nm = fmaxf(m, s);
        float sc = __expf(m - nm);   // m=-inf first iter -> 0
        float p = __expf(s - nm);
        const float4 vv = *(const float4*)(v + (size_t)sn * Dd + lane * 4);
        l = l * sc + p;
        acc.x = acc.x * sc + p * vv.x;
        acc.y = acc.y * sc + p * vv.y;
        acc.z = acc.z * sc + p * vv.z;
        acc.w = acc.w * sc + p * vv.w;
        m = nm;
    }
    float inv = (l > 0.f) ? (1.f / l) : 0.f;
    float4 o = make_float4(acc.x * inv, acc.y * inv, acc.z * inv, acc.w * inv);
    *(float4*)(out + (size_t)gwarp * Dd + lane * 4) = o;
}

// ---------------- BatchNorm (training-mode, over node dim) ----------------
__global__ void zero_sums_kernel() {
    int t = threadIdx.x;
    if (t < Dd) { g_sum[t] = 0.f; g_sumsq[t] = 0.f; }
}

__global__ void bn_reduce_kernel(const float* __restrict__ a, const float* __restrict__ b) {
    int col = threadIdx.x;  // 128 threads
    int rows = (Nn + gridDim.x - 1) / gridDim.x;
    int r0 = blockIdx.x * rows;
    int r1 = r0 + rows; if (r1 > Nn) r1 = Nn;
    float s = 0.f, s2 = 0.f;
    for (int r = r0; r < r1; r++) {
        float t = a[(size_t)r * Dd + col] + b[(size_t)r * Dd + col];
        s += t;
        s2 += t * t;
    }
    atomicAdd(&g_sum[col], s);
    atomicAdd(&g_sumsq[col], s2);
}

__global__ void bn_finalize_kernel(const float* __restrict__ gamma, const float* __restrict__ beta) {
    int c = threadIdx.x;
    if (c < Dd) {
        float mean = g_sum[c] / (float)Nn;
        float var = g_sumsq[c] / (float)Nn - mean * mean;
        float rstd = rsqrtf(var + BN_EPS);
        float sc = rstd * gamma[c];
        g_scale[c] = sc;
        g_shift[c] = beta[c] - mean * sc;
    }
}

__global__ void bn_apply_kernel(const float* __restrict__ a, const float* __restrict__ b,
                                float* __restrict__ o) {
    size_t idx = (size_t)blockIdx.x * blockDim.x + threadIdx.x;
    size_t stride = (size_t)gridDim.x * blockDim.x;
    size_t total = (size_t)Nn * Dd;
    for (; idx < total; idx += stride) {
        int col = (int)(idx & (Dd - 1));
        o[idx] = (a[idx] + b[idx]) * g_scale[col] + g_shift[col];
    }
}

// ---------------- final projection [N,128] @ [128,5] + bias ----------------
__global__ void proj_kernel(const float* __restrict__ x, const float* __restrict__ Wp,
                            const float* __restrict__ bp, float* __restrict__ out) {
    __shared__ float w[Dd * CC];
    for (int i = threadIdx.x; i < Dd * CC; i += blockDim.x) w[i] = Wp[i];
    __syncthreads();
    int n = blockIdx.x * blockDim.x + threadIdx.x;
    if (n >= Nn) return;
    float acc[CC];
#pragma unroll
    for (int c = 0; c < CC; c++) acc[c] = bp[c];
    const float* xr = x + (size_t)n * Dd;
    for (int kk = 0; kk < Dd; kk += 4) {
        float4 xv = *(const float4*)(xr + kk);
#pragma unroll
        for (int c = 0; c < CC; c++) {
            acc[c] += xv.x * w[(kk + 0) * CC + c];
            acc[c] += xv.y * w[(kk + 1) * CC + c];
            acc[c] += xv.z * w[(kk + 2) * CC + c];
            acc[c] += xv.w * w[(kk + 3) * CC + c];
        }
    }
#pragma unroll
    for (int c = 0; c < CC; c++) out[(size_t)n * CC + c] = acc[c];
}

// ---------------- driver ----------------
extern "C" void kernel_launch(void* const* d_in, const int* in_sizes, int n_in,
                              void* d_out, int out_size) {
    const float* x_in = (const float*)d_in[0];
    const int* eidx = (const int*)d_in[1];
    const float* Wq = (const float*)d_in[2];
    const float* Wk = (const float*)d_in[3];
    const float* Wv = (const float*)d_in[4];
    const float* Wo = (const float*)d_in[5];
    const float* g1 = (const float*)d_in[6];
    const float* bn1 = (const float*)d_in[7];
    const float* W1 = (const float*)d_in[8];
    const float* bf1 = (const float*)d_in[9];
    const float* W2 = (const float*)d_in[10];
    const float* bf2 = (const float*)d_in[11];
    const float* g2 = (const float*)d_in[12];
    const float* bn2 = (const float*)d_in[13];
    const float* Wp = (const float*)d_in[14];
    const float* bp = (const float*)d_in[15];
    float* out = (float*)d_out;

    const int* src = eidx;        // edge_index[0]
    const int* dst = eidx + Ee;   // edge_index[1]

    dim3 gemmGrid1((Nn + 127) / 128, 1);   // Nc=128
    dim3 gemmGrid2((Nn + 127) / 128, 2);   // Nc=256
    int attnBlocks = (Nn * 32 + 255) / 256;
    int numChunks = (Nn + 1023) / 1024;    // 49

    // launches 1-3: input copy + CSR init
    copy_in_kernel<<<2048, 256>>>(x_in, g_X, Nn * Dd);
    zero_csr_kernel<<<256, 256>>>();
    count_kernel<<<(Ee + 255) / 256, 256>>>(dst);

    // launches 4-6: layer-0 Q/K/V GEMMs (positioned so the profiler window
    // -s 5 -c 1 captures a GEMM). They depend only on copy_in (stream-ordered).
    gemm_kernel<<<gemmGrid1, 256>>>(g_X, Wq, nullptr, g_Q, Nn, Dd, Dd, 0);
    gemm_kernel<<<gemmGrid1, 256>>>(g_X, Wk, nullptr, g_K, Nn, Dd, Dd, 0);
    gemm_kernel<<<gemmGrid1, 256>>>(g_X, Wv, nullptr, g_V, Nn, Dd, Dd, 0);

    // finish CSR build (all before the first attn, stream-ordered)
    scan_chunk_kernel<<<numChunks, 1024>>>();
    scan_blocks_kernel<<<1, 32>>>(numChunks);
    scan_add_kernel<<<(Nn + 255) / 256, 256>>>();
    fill_kernel<<<(Ee + 255) / 256, 256>>>(src, dst);

    for (int i = 0; i < LL; i++) {
        const float* Wq_i = Wq + (size_t)i * Dd * Dd;
        const float* Wk_i = Wk + (size_t)i * Dd * Dd;
        const float* Wv_i = Wv + (size_t)i * Dd * Dd;
        const float* Wo_i = Wo + (size_t)i * Dd * Dd;
        const float* W1_i = W1 + (size_t)i * Dd * FFd;
        const float* W2_i = W2 + (size_t)i * FFd * Dd;

        if (i > 0) {
            gemm_kernel<<<gemmGrid1, 256>>>(g_X, Wq_i, nullptr, g_Q, Nn, Dd, Dd, 0);
            gemm_kernel<<<gemmGrid1, 256>>>(g_X, Wk_i, nullptr, g_K, Nn, Dd, Dd, 0);
            gemm_kernel<<<gemmGrid1, 256>>>(g_X, Wv_i, nullptr, g_V, Nn, Dd, Dd, 0);
        }

        attn_kernel<<<attnBlocks, 256>>>(g_Q, g_K, g_V, g_ATT);

        gemm_kernel<<<gemmGrid1, 256>>>(g_ATT, Wo_i, nullptr, g_A, Nn, Dd, Dd, 0);

        // x = BN(a + x)
        zero_sums_kernel<<<1, 128>>>();
        bn_reduce_kernel<<<256, 128>>>(g_A, g_X);
        bn_finalize_kernel<<<1, 128>>>(g1 + (size_t)i * Dd, bn1 + (size_t)i * Dd);
        bn_apply_kernel<<<2048, 256>>>(g_A, g_X, g_X);

        // h = relu(x@W1 + bf1); t = h@W2 + bf2
        gemm_kernel<<<gemmGrid2, 256>>>(g_X, W1_i, bf1 + (size_t)i * FFd, g_Hbuf, Nn, Dd, FFd, 1);
        gemm_kernel<<<gemmGrid1, 256>>>(g_Hbuf, W2_i, bf2 + (size_t)i * Dd, g_T, Nn, FFd, Dd, 0);

        // x = BN(x + t)
        zero_sums_kernel<<<1, 128>>>();
        bn_reduce_kernel<<<256, 128>>>(g_X, g_T);
        bn_finalize_kernel<<<1, 128>>>(g2 + (size_t)i * Dd, bn2 + (size_t)i * Dd);
        bn_apply_kernel<<<2048, 256>>>(g_X, g_T, g_X);
    }

    proj_kernel<<<(Nn + 255) / 256, 256>>>(g_X, Wp, bp, out);

    (void)in_sizes; (void)n_in; (void)out_size;
}

// round 4
// speedup vs baseline: 1.0271x; 1.0271x over previous
#include <cuda_runtime.h>
#include <math.h>

#define Nn 50000
#define Ee 640000
#define Dd 128
#define FFd 256
#define CC 5
#define LL 6
#define BN_EPS 1e-5f

// ---------------- static scratch (no allocations allowed) ----------------
__device__ float g_X[(size_t)Nn * Dd];
__device__ float g_Q[(size_t)Nn * Dd];
__device__ float g_K[(size_t)Nn * Dd];
__device__ float g_V[(size_t)Nn * Dd];
__device__ float g_ATT[(size_t)Nn * Dd];
__device__ float g_A[(size_t)Nn * Dd];
__device__ float g_Hbuf[(size_t)Nn * FFd];
__device__ float g_T[(size_t)Nn * Dd];

__device__ int g_cnt[Nn];
__device__ int g_fill[Nn];
__device__ int g_rowptr[Nn + 1];
__device__ int g_esrc[Ee];
__device__ int g_blocksum[64];

__device__ float g_sum[Dd];
__device__ float g_sumsq[Dd];
__device__ float g_scale[Dd];
__device__ float g_shift[Dd];

// ---------------- small utility kernels ----------------
__global__ void copy_in_kernel(const float* __restrict__ src, float* __restrict__ dst, int n) {
    int i = blockIdx.x * blockDim.x + threadIdx.x;
    int stride = gridDim.x * blockDim.x;
    for (; i < n; i += stride) dst[i] = src[i];
}

__global__ void zero_csr_kernel() {
    int i = blockIdx.x * blockDim.x + threadIdx.x;
    int stride = gridDim.x * blockDim.x;
    for (; i < Nn; i += stride) { g_cnt[i] = 0; g_fill[i] = 0; }
}

__global__ void count_kernel(const int* __restrict__ dst) {
    int e = blockIdx.x * blockDim.x + threadIdx.x;
    if (e < Ee) atomicAdd(&g_cnt[dst[e]], 1);
}

// inclusive scan per 1024-chunk -> g_rowptr[i+1], chunk totals -> g_blocksum
__global__ void scan_chunk_kernel() {
    __shared__ int s[1024];
    int tid = threadIdx.x;
    int i = blockIdx.x * 1024 + tid;
    int v = (i < Nn) ? g_cnt[i] : 0;
    s[tid] = v;
    __syncthreads();
    for (int off = 1; off < 1024; off <<= 1) {
        int t = 0;
        if (tid >= off) t = s[tid - off];
        __syncthreads();
        s[tid] += t;
        __syncthreads();
    }
    if (i < Nn) g_rowptr[i + 1] = s[tid];
    if (tid == 1023) g_blocksum[blockIdx.x] = s[1023];
    if (blockIdx.x == 0 && tid == 0) g_rowptr[0] = 0;
}

__global__ void scan_blocks_kernel(int numChunks) {
    if (threadIdx.x == 0 && blockIdx.x == 0) {
        int run = 0;
        for (int c = 0; c < numChunks; c++) {
            int t = g_blocksum[c];
            g_blocksum[c] = run;
            run += t;
        }
    }
}

__global__ void scan_add_kernel() {
    int i = blockIdx.x * blockDim.x + threadIdx.x;
    if (i < Nn) g_rowptr[i + 1] += g_blocksum[i >> 10];
}

__global__ void fill_kernel(const int* __restrict__ src, const int* __restrict__ dst) {
    int e = blockIdx.x * blockDim.x + threadIdx.x;
    if (e < Ee) {
        int d = dst[e];
        int pos = atomicAdd(&g_fill[d], 1);
        g_esrc[g_rowptr[d] + pos] = src[e];
    }
}

// ---------------- GEMM: C[M,Nc] = A[M,K] @ B[K,Nc] (+bias)(+relu) ----------------
// BM=BN=128, BK=8, 256 threads, 8x8 per thread, fp32.
// Double-buffered smem mainloop: prefetch tile k0+8 via LDG while computing
// tile k0 from smem; scoreboard wait lands at the STS after ~512 FFMAs, so
// global latency is hidden. One barrier per iteration.
__global__ __launch_bounds__(256) void gemm_kernel(
    const float* __restrict__ A, const float* __restrict__ B,
    const float* __restrict__ bias, float* __restrict__ C,
    int M, int K, int Nc, int fuseRelu)
{
    __shared__ float As[2][8][128];
    __shared__ float Bs[2][8][128];
    int tid = threadIdx.x;
    int bm = blockIdx.x * 128;
    int bn = blockIdx.y * 128;
    int tx = tid & 15;        // 0..15 -> cols
    int ty = tid >> 4;        // 0..15 -> rows
    float acc[8][8];
#pragma unroll
    for (int i = 0; i < 8; i++)
#pragma unroll
        for (int j = 0; j < 8; j++) acc[i][j] = 0.f;

    int arow = tid >> 1;            // 0..127
    int acol = (tid & 1) * 4;       // 0 or 4
    int brow = tid >> 5;            // 0..7
    int bcol = (tid & 31) * 4;      // 0..124
    int garow = bm + arow;
    const bool aval = garow < M;
    const float* Aptr = A + (size_t)garow * K + acol;
    const float* Bptr = B + (size_t)brow * Nc + bn + bcol;

    // preload tile 0
    float4 av = make_float4(0.f, 0.f, 0.f, 0.f);
    if (aval) av = *(const float4*)(Aptr);
    float4 bv = *(const float4*)(Bptr);
    As[0][acol + 0][arow] = av.x;
    As[0][acol + 1][arow] = av.y;
    As[0][acol + 2][arow] = av.z;
    As[0][acol + 3][arow] = av.w;
    *(float4*)&Bs[0][brow][bcol] = bv;
    __syncthreads();

    int buf = 0;
    for (int k0 = 0; k0 < K; k0 += 8) {
        const int nk = k0 + 8;
        const bool has = nk < K;
        float4 av2, bv2;
        if (has) {
            av2 = make_float4(0.f, 0.f, 0.f, 0.f);
            if (aval) av2 = *(const float4*)(Aptr + nk);
            bv2 = *(const float4*)(Bptr + (size_t)nk * Nc);
        }
#pragma unroll
        for (int k = 0; k < 8; k++) {
            float ar[8], br[8];
            *(float4*)&ar[0] = *(const float4*)&As[buf][k][ty * 8];
            *(float4*)&ar[4] = *(const float4*)&As[buf][k][ty * 8 + 4];
            *(float4*)&br[0] = *(const float4*)&Bs[buf][k][tx * 8];
            *(float4*)&br[4] = *(const float4*)&Bs[buf][k][tx * 8 + 4];
#pragma unroll
            for (int i = 0; i < 8; i++)
#pragma unroll
                for (int j = 0; j < 8; j++) acc[i][j] += ar[i] * br[j];
        }
        if (has) {
            int nb = buf ^ 1;
            As[nb][acol + 0][arow] = av2.x;
            As[nb][acol + 1][arow] = av2.y;
            As[nb][acol + 2][arow] = av2.z;
            As[nb][acol + 3][arow] = av2.w;
            *(float4*)&Bs[nb][brow][bcol] = bv2;
            __syncthreads();
            buf = nb;
        }
    }

    float bvals[8];
#pragma unroll
    for (int j = 0; j < 8; j++) bvals[j] = bias ? bias[bn + tx * 8 + j] : 0.f;

#pragma unroll
    for (int i = 0; i < 8; i++) {
        int row = bm + ty * 8 + i;
        if (row < M) {
            float o[8];
#pragma unroll
            for (int j = 0; j < 8; j++) {
                float v = acc[i][j] + bvals[j];
                if (fuseRelu) v = fmaxf(v, 0.f);
                o[j] = v;
            }
            float* cp = C + (size_t)row * Nc + bn + tx * 8;
            *(float4*)cp = *(float4*)&o[0];
            *(float4*)(cp + 4) = *(float4*)&o[4];
        }
    }
}

// ---------------- edge-restricted MHA: one warp per dst node, online softmax ----------------
__global__ __launch_bounds__(256) void attn_kernel(
    const float* __restrict__ q, const float* __restrict__ k,
    const float* __restrict__ v, float* __restrict__ out)
{
    int gwarp = (blockIdx.x * blockDim.x + threadIdx.x) >> 5;
    if (gwarp >= Nn) return;
    int lane = threadIdx.x & 31;

    float4 qv = *(const float4*)(q + (size_t)gwarp * Dd + lane * 4);
    float m = -INFINITY;
    float l = 0.f;
    float4 acc = make_float4(0.f, 0.f, 0.f, 0.f);

    int beg = g_rowptr[gwarp];
    int end = g_rowptr[gwarp + 1];
    for (int it = beg; it < end; it++) {
        int sn = g_esrc[it];
        const float4 kv = *(const float4*)(k + (size_t)sn * Dd + lane * 4);
        float partial = qv.x * kv.x + qv.y * kv.y + qv.z * kv.z + qv.w * kv.w;
        // reduce over the 4 lanes covering one head (DH=16 = 4 lanes x 4 floats)
        partial += __shfl_xor_sync(0xffffffffu, partial, 1);
        partial += __shfl_xor_sync(0xffffffffu, partial, 2);
        float s = partial * 0.25f;   // 1/sqrt(16)
        float nm = fmaxf(m, s);
        float sc = __expf(m - nm);   // m=-inf first iter -> 0
        float p = __expf(s - nm);
        const float4 vv = *(const float4*)(v + (size_t)sn * Dd + lane * 4);
        l = l * sc + p;
        acc.x = acc.x * sc + p * vv.x;
        acc.y = acc.y * sc + p * vv.y;
        acc.z = acc.z * sc + p * vv.z;
        acc.w = acc.w * sc + p * vv.w;
        m = nm;
    }
    float inv = (l > 0.f) ? (1.f / l) : 0.f;
    float4 o = make_float4(acc.x * inv, acc.y * inv, acc.z * inv, acc.w * inv);
    *(float4*)(out + (size_t)gwarp * Dd + lane * 4) = o;
}

// ---------------- BatchNorm (training-mode, over node dim) ----------------
__global__ void zero_sums_kernel() {
    int t = threadIdx.x;
    if (t < Dd) { g_sum[t] = 0.f; g_sumsq[t] = 0.f; }
}

__global__ void bn_reduce_kernel(const float* __restrict__ a, const float* __restrict__ b) {
    int col = threadIdx.x;  // 128 threads
    int rows = (Nn + gridDim.x - 1) / gridDim.x;
    int r0 = blockIdx.x * rows;
    int r1 = r0 + rows; if (r1 > Nn) r1 = Nn;
    float s = 0.f, s2 = 0.f;
    for (int r = r0; r < r1; r++) {
        float t = a[(size_t)r * Dd + col] + b[(size_t)r * Dd + col];
        s += t;
        s2 += t * t;
    }
    atomicAdd(&g_sum[col], s);
    atomicAdd(&g_sumsq[col], s2);
}

__global__ void bn_finalize_kernel(const float* __restrict__ gamma, const float* __restrict__ beta) {
    int c = threadIdx.x;
    if (c < Dd) {
        float mean = g_sum[c] / (float)Nn;
        float var = g_sumsq[c] / (float)Nn - mean * mean;
        float rstd = rsqrtf(var + BN_EPS);
        float sc = rstd * gamma[c];
        g_scale[c] = sc;
        g_shift[c] = beta[c] - mean * sc;
    }
}

__global__ void bn_apply_kernel(const float* __restrict__ a, const float* __restrict__ b,
                                float* __restrict__ o) {
    size_t idx = (size_t)blockIdx.x * blockDim.x + threadIdx.x;
    size_t stride = (size_t)gridDim.x * blockDim.x;
    size_t total = (size_t)Nn * Dd;
    for (; idx < total; idx += stride) {
        int col = (int)(idx & (Dd - 1));
        o[idx] = (a[idx] + b[idx]) * g_scale[col] + g_shift[col];
    }
}

// ---------------- final projection [N,128] @ [128,5] + bias ----------------
__global__ void proj_kernel(const float* __restrict__ x, const float* __restrict__ Wp,
                            const float* __restrict__ bp, float* __restrict__ out) {
    __shared__ float w[Dd * CC];
    for (int i = threadIdx.x; i < Dd * CC; i += blockDim.x) w[i] = Wp[i];
    __syncthreads();
    int n = blockIdx.x * blockDim.x + threadIdx.x;
    if (n >= Nn) return;
    float acc[CC];
#pragma unroll
    for (int c = 0; c < CC; c++) acc[c] = bp[c];
    const float* xr = x + (size_t)n * Dd;
    for (int kk = 0; kk < Dd; kk += 4) {
        float4 xv = *(const float4*)(xr + kk);
#pragma unroll
        for (int c = 0; c < CC; c++) {
            acc[c] += xv.x * w[(kk + 0) * CC + c];
            acc[c] += xv.y * w[(kk + 1) * CC + c];
            acc[c] += xv.z * w[(kk + 2) * CC + c];
            acc[c] += xv.w * w[(kk + 3) * CC + c];
        }
    }
#pragma unroll
    for (int c = 0; c < CC; c++) out[(size_t)n * CC + c] = acc[c];
}

// ---------------- driver ----------------
extern "C" void kernel_launch(void* const* d_in, const int* in_sizes, int n_in,
                              void* d_out, int out_size) {
    const float* x_in = (const float*)d_in[0];
    const int* eidx = (const int*)d_in[1];
    const float* Wq = (const float*)d_in[2];
    const float* Wk = (const float*)d_in[3];
    const float* Wv = (const float*)d_in[4];
    const float* Wo = (const float*)d_in[5];
    const float* g1 = (const float*)d_in[6];
    const float* bn1 = (const float*)d_in[7];
    const float* W1 = (const float*)d_in[8];
    const float* bf1 = (const float*)d_in[9];
    const float* W2 = (const float*)d_in[10];
    const float* bf2 = (const float*)d_in[11];
    const float* g2 = (const float*)d_in[12];
    const float* bn2 = (const float*)d_in[13];
    const float* Wp = (const float*)d_in[14];
    const float* bp = (const float*)d_in[15];
    float* out = (float*)d_out;

    const int* src = eidx;        // edge_index[0]
    const int* dst = eidx + Ee;   // edge_index[1]

    dim3 gemmGrid1((Nn + 127) / 128, 1);   // Nc=128
    dim3 gemmGrid2((Nn + 127) / 128, 2);   // Nc=256
    int attnBlocks = (Nn * 32 + 255) / 256;
    int numChunks = (Nn + 1023) / 1024;    // 49

    // launches 1-3: input copy + CSR init
    copy_in_kernel<<<2048, 256>>>(x_in, g_X, Nn * Dd);
    zero_csr_kernel<<<256, 256>>>();
    count_kernel<<<(Ee + 255) / 256, 256>>>(dst);

    // launches 4-6: layer-0 Q/K/V GEMMs (profiler window -s 5 -c 1 captures gemmV)
    gemm_kernel<<<gemmGrid1, 256>>>(g_X, Wq, nullptr, g_Q, Nn, Dd, Dd, 0);
    gemm_kernel<<<gemmGrid1, 256>>>(g_X, Wk, nullptr, g_K, Nn, Dd, Dd, 0);
    gemm_kernel<<<gemmGrid1, 256>>>(g_X, Wv, nullptr, g_V, Nn, Dd, Dd, 0);

    // finish CSR build (all before the first attn, stream-ordered)
    scan_chunk_kernel<<<numChunks, 1024>>>();
    scan_blocks_kernel<<<1, 32>>>(numChunks);
    scan_add_kernel<<<(Nn + 255) / 256, 256>>>();
    fill_kernel<<<(Ee + 255) / 256, 256>>>(src, dst);

    for (int i = 0; i < LL; i++) {
        const float* Wq_i = Wq + (size_t)i * Dd * Dd;
        const float* Wk_i = Wk + (size_t)i * Dd * Dd;
        const float* Wv_i = Wv + (size_t)i * Dd * Dd;
        const float* Wo_i = Wo + (size_t)i * Dd * Dd;
        const float* W1_i = W1 + (size_t)i * Dd * FFd;
        const float* W2_i = W2 + (size_t)i * FFd * Dd;

        if (i > 0) {
            gemm_kernel<<<gemmGrid1, 256>>>(g_X, Wq_i, nullptr, g_Q, Nn, Dd, Dd, 0);
            gemm_kernel<<<gemmGrid1, 256>>>(g_X, Wk_i, nullptr, g_K, Nn, Dd, Dd, 0);
            gemm_kernel<<<gemmGrid1, 256>>>(g_X, Wv_i, nullptr, g_V, Nn, Dd, Dd, 0);
        }

        attn_kernel<<<attnBlocks, 256>>>(g_Q, g_K, g_V, g_ATT);

        gemm_kernel<<<gemmGrid1, 256>>>(g_ATT, Wo_i, nullptr, g_A, Nn, Dd, Dd, 0);

        // x = BN(a + x)
        zero_sums_kernel<<<1, 128>>>();
        bn_reduce_kernel<<<256, 128>>>(g_A, g_X);
        bn_finalize_kernel<<<1, 128>>>(g1 + (size_t)i * Dd, bn1 + (size_t)i * Dd);
        bn_apply_kernel<<<2048, 256>>>(g_A, g_X, g_X);

        // h = relu(x@W1 + bf1); t = h@W2 + bf2
        gemm_kernel<<<gemmGrid2, 256>>>(g_X, W1_i, bf1 + (size_t)i * FFd, g_Hbuf, Nn, Dd, FFd, 1);
        gemm_kernel<<<gemmGrid1, 256>>>(g_Hbuf, W2_i, bf2 + (size_t)i * Dd, g_T, Nn, FFd, Dd, 0);

        // x = BN(x + t)
        zero_sums_kernel<<<1, 128>>>();
        bn_reduce_kernel<<<256, 128>>>(g_X, g_T);
        bn_finalize_kernel<<<1, 128>>>(g2 + (size_t)i * Dd, bn2 + (size_t)i * Dd);
        bn_apply_kernel<<<2048, 256>>>(g_X, g_T, g_X);
    }

    proj_kernel<<<(Nn + 255) / 256, 256>>>(g_X, Wp, bp, out);

    (void)in_sizes; (void)n_in; (void)out_size;
}